// round 8
// baseline (speedup 1.0000x reference)
#include <cuda_runtime.h>
#include <stdint.h>

#define N 96
#define D 64
#define C 21
#define MARGIN_F 0.3f
#define ONE_F_BITS 0x3F800000u

#define TJ 16
#define TK 16
#define SB_STRIDE 104   // uint32 stride per B-row in smem (pad: 104 mod 32 = 8 -> no bank repeat; 416 B, 16B-aligned)

// ---------------------------------------------------------------------------
// Single fused kernel.
// Block (jt, kt, i) covers out[i, j0:j0+16, k0:k0+16, :]  (96 KB of output).
//   jt > kt  : whole tile has j >= k  -> pure zero fill, no reads, no sync.
//   jt <= kt : recompute mat row i, diffs/sames row i from raw inputs (tiny,
//              L1-resident), build B tile in smem, OR-fill the output.
// out[i,j,k,n] = (sames[i,j] && sames[i,k] && j<k)
//                ? float( diffs[i,n] && (viol[i,j,n] || viol[i,k,n]) ) : 0
// where viol[i,p,n] = (mat[i,n] - mat[i,p] <= MARGIN).
// ---------------------------------------------------------------------------
__global__ __launch_bounds__(256)
void fused_kernel(const float* __restrict__ logits,
                  const float* __restrict__ labels,
                  const float* __restrict__ feat2,
                  uint4* __restrict__ out) {
    const int jt = blockIdx.x;
    const int kt = blockIdx.y;
    const int i  = blockIdx.z;
    const int t  = threadIdx.x;             // 0..255

    const int j0 = jt * TJ;
    const int k0 = kt * TK;

    const int jj   = t >> 4;                // 0..15  (this thread's j-row)
    const int lane = t & 15;                // 0..15

    // uint4 pointer to out[i][j0+jj][k0][0]; (kk,v) space flattens to kk*24+v.
    uint4* __restrict__ obase =
        out + ((size_t)((i * N + j0 + jj) * N + k0)) * 24;

    if (jt > kt) {
        // entire tile j >= k -> zeros, no reads
        const uint4 z = make_uint4(0u, 0u, 0u, 0u);
        int idx = lane;
        #pragma unroll
        for (int it = 0; it < 24; it++) {
            obase[idx] = z;
            idx += 16;
        }
        return;
    }

    __shared__ float         xs[D];         // logits row i
    __shared__ float         li[24];        // labels row i (padded)
    __shared__ float         mrow[N];       // mat[i, :]
    __shared__ unsigned char drow[N];       // diffs[i, :] (diag NOT filled)
    __shared__ unsigned char srow[128];     // sames[i, :] (padded for kk==16 probe)
    __shared__ uint32_t      sB[32 * SB_STRIDE]; // rows 0-15: j-rows, 16-31: k-rows

    if (t < D)                xs[t] = logits[i * D + t];
    else if (t < D + C)       li[t - D] = labels[i * C + (t - D)];
    if (t < 128 - N && t + N < 128) srow[N + t] = 0;   // pad tail
    __syncthreads();

    // ---- phase 1: per-n dot / norms / label structure (threads 0..95) ----
    if (t < N) {
        float sx = 0.f;
        #pragma unroll
        for (int c = 0; c < D; c++) sx += xs[c] * xs[c];
        const float inv_nx = 1.0f / fmaxf(sqrtf(sx), 1e-12f);

        const float4* yrow = (const float4*)(feat2 + t * D);
        float dot = 0.f, nyy = 0.f;
        #pragma unroll
        for (int c = 0; c < D / 4; c++) {
            const float4 y = yrow[c];
            dot += xs[4 * c + 0] * y.x + xs[4 * c + 1] * y.y
                 + xs[4 * c + 2] * y.z + xs[4 * c + 3] * y.w;
            nyy += y.x * y.x + y.y * y.y + y.z * y.z + y.w * y.w;
        }
        const float inv_ny = 1.0f / fmaxf(sqrtf(nyy), 1e-12f);
        mrow[t] = -(dot * inv_nx * inv_ny);

        float ld = 0.f;
        #pragma unroll
        for (int c = 0; c < C; c++) ld += li[c] * labels[t * C + c];
        const bool share = (ld > 0.0f);
        drow[t] = share ? 0 : 1;                    // diag kept (matches ref)
        srow[t] = (share && (t != i)) ? 1 : 0;
    }
    __syncthreads();

    // ---- phase 1.5: B tile in smem.  32 rows x 96 words; 12 words/thread ----
    {
        const int r  = t >> 3;                      // row 0..31
        const int n0 = (t & 7) * 12;                // word start
        const int p  = (r < TJ) ? (j0 + r) : (k0 + r - TJ);
        const float mp = mrow[p];
        uint32_t* dst = &sB[r * SB_STRIDE + n0];
        #pragma unroll
        for (int q = 0; q < 12; q++) {
            const int nn = n0 + q;
            dst[q] = (drow[nn] && (mrow[nn] - mp <= MARGIN_F)) ? ONE_F_BITS : 0u;
        }
    }
    __syncthreads();

    // ---- phase 2: stream the tile out -----------------------------------
    const uint32_t* aRow = &sB[jj * SB_STRIDE];
    const uint32_t* bRow = &sB[TJ * SB_STRIDE];     // kk = 0
    const bool sj  = srow[j0 + jj] != 0;
    const int  jgl = j0 + jj;

    int idx = lane;                                  // flattened kk*24+v
    int v   = lane;                                  // lane < 16 < 24
    int kk  = 0;
    uint32_t mask = (sj && srow[k0] && (jgl < k0)) ? 0xFFFFFFFFu : 0u;

    #pragma unroll
    for (int it = 0; it < 24; it++) {
        const uint4 a = *(const uint4*)(aRow + 4 * v);
        const uint4 b = *(const uint4*)(bRow + 4 * v);
        uint4 w;
        w.x = (a.x | b.x) & mask;
        w.y = (a.y | b.y) & mask;
        w.z = (a.z | b.z) & mask;
        w.w = (a.w | b.w) & mask;
        obase[idx] = w;

        idx += 16;
        v   += 16;
        if (v >= 24) {                               // kk bump (at most once)
            v -= 24;
            kk += 1;
            bRow += SB_STRIDE;
            mask = (sj && srow[k0 + kk] && (jgl < k0 + kk)) ? 0xFFFFFFFFu : 0u;
        }
    }
}

// ---------------------------------------------------------------------------
extern "C" void kernel_launch(void* const* d_in, const int* in_sizes, int n_in,
                              void* d_out, int out_size) {
    const float* logits = (const float*)d_in[0];   // [96, 64]
    const float* labels = (const float*)d_in[1];   // [96, 21]
    const float* feat2  = (const float*)d_in[2];   // [96, 64]

    fused_kernel<<<dim3(N / TJ, N / TK, N), 256>>>(logits, labels, feat2,
                                                   (uint4*)d_out);
}

// round 9
// speedup vs baseline: 1.3490x; 1.3490x over previous
#include <cuda_runtime.h>
#include <stdint.h>

#define N 96
#define D 64
#define C 21
#define MARGIN_F 0.3f
#define ONE_F_BITS 0x3F800000u

#define TJ 8
#define TK 8
#define NT 12                   // tiles per axis (96/8)
#define NZPAIR 66               // #(jt,kt) with jt>kt
#define NWPAIR 78               // #(jt,kt) with jt<=kt

// Scratch (no allocations allowed in kernel_launch)
__device__ unsigned char  g_sames[N * N];
// B[i,p,n] float-encoded (0x0 / 0x3F800000), 24 uint4 per (i,p). 3.4 MB, L2-resident.
__device__ uint4          g_B4[N * N * 24];

// ---------------------------------------------------------------------------
// Kernel 1: fused prep + zero-fill.
//   blocks [0, 96)            : prep for i = bid  (R7-proven code, threads<96)
//   blocks [96, 96+66*96)     : zero-fill tile (i, jt>kt) — no dependency on prep
// ---------------------------------------------------------------------------
__global__ __launch_bounds__(256)
void prep_zero_kernel(const float* __restrict__ logits,
                      const float* __restrict__ labels,
                      const float* __restrict__ feat2,
                      uint4* __restrict__ out) {
    const int bid = blockIdx.x;
    const int t   = threadIdx.x;

    if (bid >= N) {
        // ---------------- zero-fill role ----------------
        const int z = bid - N;
        const int i = z / NZPAIR;
        const int p = z - i * NZPAIR;
        // p -> (jt, kt) with jt>kt:  p = jt*(jt-1)/2 + kt
        int jt = 1;
        while ((jt * (jt + 1)) / 2 <= p) jt++;
        const int kt = p - (jt * (jt - 1)) / 2;

        const int jj   = t >> 5;            // 0..7 (8 j-rows, 32 lanes each)
        const int lane = t & 31;
        // out[i][jt*8+jj][kt*8][0] as uint4; row covers 8*24 = 192 uint4
        uint4* __restrict__ obase =
            out + ((size_t)((i * N + jt * TJ + jj) * N + kt * TK)) * 24;

        const uint4 zv = make_uint4(0u, 0u, 0u, 0u);
        #pragma unroll
        for (int it = 0; it < 6; it++)
            __stcs(&obase[it * 32 + lane], zv);
        return;
    }

    // ---------------- prep role (i = bid), threads 0..95 active ----------------
    const int i = bid;
    const int j = t;

    __shared__ float         xs[D];
    __shared__ float         li[C];
    __shared__ float         inv_nx;
    __shared__ float         mrow[N];
    __shared__ unsigned char drow[N];

    if (j < D) xs[j] = logits[i * D + j];
    if (j < C) li[j] = labels[i * C + j];
    __syncthreads();

    if (j == 0) {
        float s = 0.f;
        #pragma unroll
        for (int c = 0; c < D; c++) s += xs[c] * xs[c];
        inv_nx = 1.0f / fmaxf(sqrtf(s), 1e-12f);
    }
    __syncthreads();

    if (j < N) {
        float dot = 0.f, nyy = 0.f;
        #pragma unroll
        for (int c = 0; c < D; c++) {
            float y = feat2[j * D + c];
            dot += xs[c] * y;
            nyy += y * y;
        }
        const float inv_ny = 1.0f / fmaxf(sqrtf(nyy), 1e-12f);
        mrow[j] = -(dot * inv_nx * inv_ny);

        float ld = 0.f;
        #pragma unroll
        for (int c = 0; c < C; c++) ld += li[c] * labels[j * C + c];
        const bool share = (ld > 0.0f);
        g_sames[i * N + j] = (share && (i != j)) ? 1 : 0;
        drow[j] = share ? 0 : 1;             // diagonal NOT filled (matches ref)
    }
    __syncthreads();

    if (j < N) {
        const float mp = mrow[j];
        uint32_t w[N];
        #pragma unroll
        for (int nn = 0; nn < N; nn++)
            w[nn] = (drow[nn] && (mrow[nn] - mp <= MARGIN_F)) ? ONE_F_BITS : 0u;

        uint4* dst = &g_B4[(i * N + j) * 24];
        #pragma unroll
        for (int v = 0; v < 24; v++)
            dst[v] = make_uint4(w[4 * v + 0], w[4 * v + 1], w[4 * v + 2], w[4 * v + 3]);
    }
}

// ---------------------------------------------------------------------------
// Kernel 2: work-fill over jt<=kt tile-pairs only (R7-proven hot path).
// Grid: (78, 96) = (pair, i), 256 threads.
// ---------------------------------------------------------------------------
__global__ __launch_bounds__(256)
void work_fill_kernel(uint4* __restrict__ out) {
    const int p = blockIdx.x;               // 0..77
    const int i = blockIdx.y;
    const int tid = threadIdx.x;

    // p -> (jt, kt) with jt<=kt (row jt has 12-jt entries)
    int jt = 0, acc = 0;
    while (acc + (NT - jt) <= p) { acc += NT - jt; jt++; }
    const int kt = jt + (p - acc);

    const int j0 = jt * TJ;
    const int k0 = kt * TK;

    uint4* __restrict__ obase = out + ((size_t)(i * N + j0) * N + k0) * 24;

    __shared__ uint4         sBj[TJ][24];
    __shared__ uint4         sBk[TK][24];
    __shared__ unsigned char ssj[TJ];
    __shared__ unsigned char ssk[TK];

    // load 384 uint4 (rows 0-7 -> sBj, 8-15 -> sBk)
    {
        int l = tid;
        {
            const int row = l / 24, v = l % 24;
            const int src_p = (row < TJ) ? (j0 + row) : (k0 + row - TJ);
            uint4 val = g_B4[(i * N + src_p) * 24 + v];
            if (row < TJ) sBj[row][v] = val; else sBk[row - TJ][v] = val;
        }
        l = tid + 256;
        if (l < 384) {
            const int row = l / 24, v = l % 24;
            const int src_p = (row < TJ) ? (j0 + row) : (k0 + row - TJ);
            uint4 val = g_B4[(i * N + src_p) * 24 + v];
            if (row < TJ) sBj[row][v] = val; else sBk[row - TJ][v] = val;
        }
        if (tid < TJ)            ssj[tid] = g_sames[i * N + j0 + tid];
        else if (tid < TJ + TK)  ssk[tid - TJ] = g_sames[i * N + k0 + (tid - TJ)];
    }
    __syncthreads();

    const bool diag = (jt == kt);
    const uint4 z = make_uint4(0u, 0u, 0u, 0u);

    #pragma unroll
    for (int it = 0; it < 6; it++) {
        const int l  = it * 256 + tid;           // 0..1535
        const int jj = l / (TK * 24);
        const int r  = l - jj * (TK * 24);
        const int kk = r / 24;
        const int v  = r - kk * 24;

        const bool valid = ssj[jj] && ssk[kk] && (!diag || jj < kk);
        uint4 res = z;
        if (valid) {
            const uint4 a = sBj[jj][v];
            const uint4 b = sBk[kk][v];
            res = make_uint4(a.x | b.x, a.y | b.y, a.z | b.z, a.w | b.w);
        }
        __stcs(&obase[(size_t)jj * (N * 24) + r], res);
    }
}

// ---------------------------------------------------------------------------
extern "C" void kernel_launch(void* const* d_in, const int* in_sizes, int n_in,
                              void* d_out, int out_size) {
    const float* logits = (const float*)d_in[0];   // [96, 64]
    const float* labels = (const float*)d_in[1];   // [96, 21]
    const float* feat2  = (const float*)d_in[2];   // [96, 64]

    // Kernel 1: 96 prep blocks + 66*96 zero-fill blocks (prep hidden under stores)
    prep_zero_kernel<<<N + NZPAIR * N, 256>>>(logits, labels, feat2,
                                              (uint4*)d_out);
    // Kernel 2: 78*96 work blocks
    work_fill_kernel<<<dim3(NWPAIR, N), 256>>>((uint4*)d_out);
}

// round 11
// speedup vs baseline: 1.3934x; 1.0329x over previous
#include <cuda_runtime.h>
#include <stdint.h>

#define N 96
#define D 64
#define C 21
#define MARGIN_F 0.3f
#define ONE_F_BITS 0x3F800000u

#define TJ 8
#define TK 8
#define NT 12                   // tiles per axis (96/8)

// Scratch (no allocations allowed in kernel_launch)
__device__ unsigned char  g_sames[N * N];
// B[i,p,n] float-encoded (0x0 / 0x3F800000), 24 uint4 per (i,p). 3.4 MB, L2-resident.
__device__ uint4          g_B4[N * N * 24];

// ---------------------------------------------------------------------------
// Kernel 1: prep (plane z==96) + zero-fill (planes z<96, tiles jt>kt).
// Zero-fill blocks have NO dependency on prep, so prep latency hides under
// ~156 MB of zero stores.
// ---------------------------------------------------------------------------
__global__ __launch_bounds__(256)
void prep_zero_kernel(const float* __restrict__ logits,
                      const float* __restrict__ labels,
                      const float* __restrict__ feat2,
                      uint4* __restrict__ out) {
    const int t = threadIdx.x;

    if (blockIdx.z < N) {
        // ---------------- zero-fill role ----------------
        const int jt = blockIdx.x;
        const int kt = blockIdx.y;
        if (jt <= kt) return;               // handled by work kernel
        const int i  = blockIdx.z;
        const int j0 = jt * TJ;
        const int k0 = kt * TK;

        uint4* __restrict__ obase = out + ((size_t)(i * N + j0) * N + k0) * 24;
        const uint4 zv = make_uint4(0u, 0u, 0u, 0u);
        #pragma unroll
        for (int it = 0; it < 6; it++) {
            const int l  = it * 256 + t;            // 0..1535
            const int jj = l / (TK * 24);
            const int r  = l - jj * (TK * 24);
            obase[(size_t)jj * (N * 24) + r] = zv;
        }
        return;
    }

    // ---------------- prep role ----------------
    const int i = blockIdx.y * NT + blockIdx.x;     // 0..143, use first 96
    if (i >= N) return;
    const int j = t;

    __shared__ float         xs[D];
    __shared__ float         li[C];
    __shared__ float         inv_nx;
    __shared__ float         mrow[N];
    __shared__ unsigned char drow[N];

    if (j < D) xs[j] = logits[i * D + j];
    if (j < C) li[j] = labels[i * C + j];
    __syncthreads();

    if (j == 0) {
        float s = 0.f;
        #pragma unroll
        for (int c = 0; c < D; c++) s += xs[c] * xs[c];
        inv_nx = 1.0f / fmaxf(sqrtf(s), 1e-12f);
    }
    __syncthreads();

    if (j < N) {
        float dot = 0.f, nyy = 0.f;
        #pragma unroll
        for (int c = 0; c < D; c++) {
            float y = feat2[j * D + c];
            dot += xs[c] * y;
            nyy += y * y;
        }
        const float inv_ny = 1.0f / fmaxf(sqrtf(nyy), 1e-12f);
        mrow[j] = -(dot * inv_nx * inv_ny);

        float ld = 0.f;
        #pragma unroll
        for (int c = 0; c < C; c++) ld += li[c] * labels[j * C + c];
        const bool share = (ld > 0.0f);
        g_sames[i * N + j] = (share && (i != j)) ? 1 : 0;
        drow[j] = share ? 0 : 1;             // diagonal NOT filled (matches ref)
    }
    __syncthreads();

    if (j < N) {
        const float mp = mrow[j];
        uint32_t w[N];
        #pragma unroll
        for (int nn = 0; nn < N; nn++)
            w[nn] = (drow[nn] && (mrow[nn] - mp <= MARGIN_F)) ? ONE_F_BITS : 0u;

        uint4* dst = &g_B4[(i * N + j) * 24];
        #pragma unroll
        for (int v = 0; v < 24; v++)
            dst[v] = make_uint4(w[4 * v + 0], w[4 * v + 1], w[4 * v + 2], w[4 * v + 3]);
    }
}

// ---------------------------------------------------------------------------
// Kernel 2: work-fill (R7-proven hot path, plain stores).
// Grid (12,12,96); jt>kt blocks exit immediately (zeros already written).
// ---------------------------------------------------------------------------
__global__ __launch_bounds__(256)
void work_fill_kernel(uint4* __restrict__ out) {
    const int jt = blockIdx.x;
    const int kt = blockIdx.y;
    if (jt > kt) return;                    // zero region handled by kernel 1
    const int i   = blockIdx.z;
    const int tid = threadIdx.x;

    const int j0 = jt * TJ;
    const int k0 = kt * TK;

    uint4* __restrict__ obase = out + ((size_t)(i * N + j0) * N + k0) * 24;

    __shared__ uint4         sBj[TJ][24];
    __shared__ uint4         sBk[TK][24];
    __shared__ unsigned char ssj[TJ];
    __shared__ unsigned char ssk[TK];

    // load 384 uint4 (rows 0-7 -> sBj, 8-15 -> sBk)
    {
        int l = tid;
        {
            const int row = l / 24, v = l % 24;
            const int src_p = (row < TJ) ? (j0 + row) : (k0 + row - TJ);
            uint4 val = g_B4[(i * N + src_p) * 24 + v];
            if (row < TJ) sBj[row][v] = val; else sBk[row - TJ][v] = val;
        }
        l = tid + 256;
        if (l < 384) {
            const int row = l / 24, v = l % 24;
            const int src_p = (row < TJ) ? (j0 + row) : (k0 + row - TJ);
            uint4 val = g_B4[(i * N + src_p) * 24 + v];
            if (row < TJ) sBj[row][v] = val; else sBk[row - TJ][v] = val;
        }
        if (tid < TJ)            ssj[tid] = g_sames[i * N + j0 + tid];
        else if (tid < TJ + TK)  ssk[tid - TJ] = g_sames[i * N + k0 + (tid - TJ)];
    }
    __syncthreads();

    const bool diag = (jt == kt);
    const uint4 z = make_uint4(0u, 0u, 0u, 0u);

    #pragma unroll
    for (int it = 0; it < 6; it++) {
        const int l  = it * 256 + tid;           // 0..1535
        const int jj = l / (TK * 24);
        const int r  = l - jj * (TK * 24);
        const int kk = r / 24;
        const int v  = r - kk * 24;

        const bool valid = ssj[jj] && ssk[kk] && (!diag || jj < kk);
        uint4 res = z;
        if (valid) {
            const uint4 a = sBj[jj][v];
            const uint4 b = sBk[kk][v];
            res = make_uint4(a.x | b.x, a.y | b.y, a.z | b.z, a.w | b.w);
        }
        obase[(size_t)jj * (N * 24) + r] = res;
    }
}

// ---------------------------------------------------------------------------
extern "C" void kernel_launch(void* const* d_in, const int* in_sizes, int n_in,
                              void* d_out, int out_size) {
    const float* logits = (const float*)d_in[0];   // [96, 64]
    const float* labels = (const float*)d_in[1];   // [96, 21]
    const float* feat2  = (const float*)d_in[2];   // [96, 64]

    // K1: zero-fill (jt>kt tiles) + prep blocks in z==96 plane (prep hidden)
    prep_zero_kernel<<<dim3(NT, NT, N + 1), 256>>>(logits, labels, feat2,
                                                   (uint4*)d_out);
    // K2: work-fill (jt<=kt tiles)
    work_fill_kernel<<<dim3(NT, NT, N), 256>>>((uint4*)d_out);
}

// round 12
// speedup vs baseline: 1.8390x; 1.3198x over previous
#include <cuda_runtime.h>
#include <stdint.h>

#define N 96
#define D 64
#define C 21
#define MARGIN_F 0.3f
#define ONE_F_BITS 0x3F800000u

#define TJ 8
#define TK 8
#define NZPAIR 66               // #(jt,kt) with jt>kt
#define NWPAIR 78               // #(jt,kt) with jt<=kt

#define NBLK_PREP  N                      // 96
#define NBLK_ZERO  (NZPAIR * N)           // 6336
#define NBLK_WORK  (NWPAIR * N)           // 7488
#define ZERO_BASE  NBLK_PREP              // 96
#define WORK_BASE  (NBLK_PREP + NBLK_ZERO) // 6432
#define NBLK_TOTAL (WORK_BASE + NBLK_WORK) // 13920

// Scratch (no allocations allowed in kernel_launch)
__device__ unsigned char  g_sames[N * N];
// B[i,p,n] float-encoded (0x0 / 0x3F800000), 24 uint4 per (i,p). 3.4 MB, L2-resident.
__device__ uint4          g_B4[N * N * 24];

// tile-pair lookup tables (literal -> zero decode cost)
__constant__ uint8_t ZJT[NZPAIR] = {
    1,
    2,2,
    3,3,3,
    4,4,4,4,
    5,5,5,5,5,
    6,6,6,6,6,6,
    7,7,7,7,7,7,7,
    8,8,8,8,8,8,8,8,
    9,9,9,9,9,9,9,9,9,
    10,10,10,10,10,10,10,10,10,10,
    11,11,11,11,11,11,11,11,11,11,11 };
__constant__ uint8_t ZKT[NZPAIR] = {
    0,
    0,1,
    0,1,2,
    0,1,2,3,
    0,1,2,3,4,
    0,1,2,3,4,5,
    0,1,2,3,4,5,6,
    0,1,2,3,4,5,6,7,
    0,1,2,3,4,5,6,7,8,
    0,1,2,3,4,5,6,7,8,9,
    0,1,2,3,4,5,6,7,8,9,10 };
__constant__ uint8_t WJT[NWPAIR] = {
    0,0,0,0,0,0,0,0,0,0,0,0,
    1,1,1,1,1,1,1,1,1,1,1,
    2,2,2,2,2,2,2,2,2,2,
    3,3,3,3,3,3,3,3,3,
    4,4,4,4,4,4,4,4,
    5,5,5,5,5,5,5,
    6,6,6,6,6,6,
    7,7,7,7,7,
    8,8,8,8,
    9,9,9,
    10,10,
    11 };
__constant__ uint8_t WKT[NWPAIR] = {
    0,1,2,3,4,5,6,7,8,9,10,11,
    1,2,3,4,5,6,7,8,9,10,11,
    2,3,4,5,6,7,8,9,10,11,
    3,4,5,6,7,8,9,10,11,
    4,5,6,7,8,9,10,11,
    5,6,7,8,9,10,11,
    6,7,8,9,10,11,
    7,8,9,10,11,
    8,9,10,11,
    9,10,11,
    10,11,
    11 };

// ---------------------------------------------------------------------------
// ONE kernel, roles by bid range (bid order => prep runs in wave 1, work
// blocks cannot start until the 6336 zero blocks (>=23us of stores) drain,
// by which time prep (~8us) is long complete).
// ---------------------------------------------------------------------------
__global__ __launch_bounds__(256, 6)
void miner_kernel(const float* __restrict__ logits,
                  const float* __restrict__ labels,
                  const float* __restrict__ feat2,
                  uint4* __restrict__ out) {
    const int bid = blockIdx.x;
    const int t   = threadIdx.x;

    // ======================= role 1: prep (bids 0..95) =====================
    if (bid < NBLK_PREP) {
        const int i = bid;
        const int j = t;

        __shared__ float         xs[D];
        __shared__ float         li[C];
        __shared__ float         inv_nx;
        __shared__ float         mrow[N];
        __shared__ unsigned char drow[N];

        if (j < D) xs[j] = logits[i * D + j];
        if (j < C) li[j] = labels[i * C + j];
        __syncthreads();

        if (j == 0) {
            float s = 0.f;
            #pragma unroll
            for (int c = 0; c < D; c++) s += xs[c] * xs[c];
            inv_nx = 1.0f / fmaxf(sqrtf(s), 1e-12f);
        }
        __syncthreads();

        if (j < N) {
            float dot = 0.f, nyy = 0.f;
            #pragma unroll
            for (int c = 0; c < D; c++) {
                float y = feat2[j * D + c];
                dot += xs[c] * y;
                nyy += y * y;
            }
            const float inv_ny = 1.0f / fmaxf(sqrtf(nyy), 1e-12f);
            mrow[j] = -(dot * inv_nx * inv_ny);

            float ld = 0.f;
            #pragma unroll
            for (int c = 0; c < C; c++) ld += li[c] * labels[j * C + c];
            const bool share = (ld > 0.0f);
            g_sames[i * N + j] = (share && (i != j)) ? 1 : 0;
            drow[j] = share ? 0 : 1;         // diagonal NOT filled (matches ref)
        }
        __syncthreads();

        if (j < N) {
            // lean B-row build: no big local array (keeps whole-kernel regs low)
            const float mp = mrow[j];
            uint4* dst = &g_B4[(i * N + j) * 24];
            #pragma unroll
            for (int v = 0; v < 24; v++) {
                uint4 w;
                w.x = (drow[4*v+0] && (mrow[4*v+0] - mp <= MARGIN_F)) ? ONE_F_BITS : 0u;
                w.y = (drow[4*v+1] && (mrow[4*v+1] - mp <= MARGIN_F)) ? ONE_F_BITS : 0u;
                w.z = (drow[4*v+2] && (mrow[4*v+2] - mp <= MARGIN_F)) ? ONE_F_BITS : 0u;
                w.w = (drow[4*v+3] && (mrow[4*v+3] - mp <= MARGIN_F)) ? ONE_F_BITS : 0u;
                dst[v] = w;
            }
        }
        return;
    }

    // ================= role 2: zero-fill (bids 96..6431) ===================
    if (bid < WORK_BASE) {
        const int z  = bid - ZERO_BASE;
        const int i  = z / NZPAIR;
        const int p  = z - i * NZPAIR;
        const int j0 = (int)ZJT[p] * TJ;
        const int k0 = (int)ZKT[p] * TK;

        uint4* __restrict__ obase = out + ((size_t)(i * N + j0) * N + k0) * 24;
        const uint4 zv = make_uint4(0u, 0u, 0u, 0u);
        #pragma unroll
        for (int it = 0; it < 6; it++) {
            const int l  = it * 256 + t;            // 0..1535
            const int jj = l / (TK * 24);
            const int r  = l - jj * (TK * 24);
            obase[(size_t)jj * (N * 24) + r] = zv;
        }
        return;
    }

    // ================= role 3: work-fill (bids 6432..13919) ================
    {
        const int w  = bid - WORK_BASE;
        const int i  = w / NWPAIR;
        const int q  = w - i * NWPAIR;
        const int jt = (int)WJT[q];
        const int kt = (int)WKT[q];
        const int j0 = jt * TJ;
        const int k0 = kt * TK;

        uint4* __restrict__ obase = out + ((size_t)(i * N + j0) * N + k0) * 24;

        __shared__ uint4         sBj[TJ][24];
        __shared__ uint4         sBk[TK][24];
        __shared__ unsigned char ssj[TJ];
        __shared__ unsigned char ssk[TK];

        // load 384 uint4 (rows 0-7 -> sBj, 8-15 -> sBk)
        {
            int l = t;
            {
                const int row = l / 24, v = l % 24;
                const int src_p = (row < TJ) ? (j0 + row) : (k0 + row - TJ);
                uint4 val = g_B4[(i * N + src_p) * 24 + v];
                if (row < TJ) sBj[row][v] = val; else sBk[row - TJ][v] = val;
            }
            l = t + 256;
            if (l < 384) {
                const int row = l / 24, v = l % 24;
                const int src_p = (row < TJ) ? (j0 + row) : (k0 + row - TJ);
                uint4 val = g_B4[(i * N + src_p) * 24 + v];
                if (row < TJ) sBj[row][v] = val; else sBk[row - TJ][v] = val;
            }
            if (t < TJ)            ssj[t] = g_sames[i * N + j0 + t];
            else if (t < TJ + TK)  ssk[t - TJ] = g_sames[i * N + k0 + (t - TJ)];
        }
        __syncthreads();

        const bool diag = (jt == kt);
        const uint4 z = make_uint4(0u, 0u, 0u, 0u);

        #pragma unroll
        for (int it = 0; it < 6; it++) {
            const int l  = it * 256 + t;             // 0..1535
            const int jj = l / (TK * 24);
            const int r  = l - jj * (TK * 24);
            const int kk = r / 24;
            const int v  = r - kk * 24;

            const bool valid = ssj[jj] && ssk[kk] && (!diag || jj < kk);
            uint4 res = z;
            if (valid) {
                const uint4 a = sBj[jj][v];
                const uint4 b = sBk[kk][v];
                res = make_uint4(a.x | b.x, a.y | b.y, a.z | b.z, a.w | b.w);
            }
            obase[(size_t)jj * (N * 24) + r] = res;
        }
    }
}

// ---------------------------------------------------------------------------
extern "C" void kernel_launch(void* const* d_in, const int* in_sizes, int n_in,
                              void* d_out, int out_size) {
    const float* logits = (const float*)d_in[0];   // [96, 64]
    const float* labels = (const float*)d_in[1];   // [96, 21]
    const float* feat2  = (const float*)d_in[2];   // [96, 64]

    miner_kernel<<<NBLK_TOTAL, 256>>>(logits, labels, feat2, (uint4*)d_out);
}